// round 11
// baseline (speedup 1.0000x reference)
#include <cuda_runtime.h>
#include <cuda_fp16.h>
#include <math.h>
#include <stdint.h>

#define N_NODES 50000
#define N_EDGES 1600000
#define E_TOT   (N_EDGES + N_NODES)
#define HID     128
#define SLOPE   0.2f

typedef unsigned long long u64;

// ------------------------- device scratch (no allocs allowed) ---------------
__device__ float g_XL[(size_t)N_NODES * HID];
__device__ float g_XR[(size_t)N_NODES * HID];
__device__ float g_H1[(size_t)N_NODES * HID];
__device__ int   g_DEG[N_NODES];        // zero-init; k_scanf re-zeroes
__device__ int   g_ROWPTR[N_NODES + 1];
__device__ int   g_CURSOR[N_NODES];
__device__ int   g_CSR[E_TOT];
__device__ int   g_PART[64];            // zeroed by k_hist block 0

// ------------------------- packed f32x2 helpers -------------------------------
__device__ __forceinline__ u64 pk2(float lo, float hi) {
    u64 r;
    asm("mov.b64 %0, {%1, %2};" : "=l"(r) : "f"(lo), "f"(hi));
    return r;
}
__device__ __forceinline__ void upk2(u64 v, float& lo, float& hi) {
    asm("mov.b64 {%0, %1}, %2;" : "=f"(lo), "=f"(hi) : "l"(v));
}
__device__ __forceinline__ u64 fma2(u64 a, u64 b, u64 c) {
    u64 d;
    asm("fma.rn.f32x2 %0, %1, %2, %3;" : "=l"(d) : "l"(a), "l"(b), "l"(c));
    return d;
}
__device__ __forceinline__ u64 add2(u64 a, u64 b) {
    u64 d;
    asm("add.rn.f32x2 %0, %1, %2;" : "=l"(d) : "l"(a), "l"(b));
    return d;
}
__device__ __forceinline__ u64 abs2(u64 a) {
    return a & 0x7FFFFFFF7FFFFFFFULL;   // clears both sign bits (2x LOP3, alu pipe)
}

// ------------------------- edge dtype helpers --------------------------------
__device__ __forceinline__ int detect_is64(const void* e) {
    int flag = (((const int*)e)[2 * threadIdx.x + 1] != 0);
    return !__syncthreads_or(flag);
}
__device__ __forceinline__ int edge_val(const void* e, int is64, int idx) {
    return is64 ? (int)((const long long*)e)[idx] : ((const int*)e)[idx];
}

// ------------------------- CSR build (R8 form) --------------------------------
__global__ __launch_bounds__(256) void k_hist(const void* __restrict__ e) {
    if (blockIdx.x == 0 && threadIdx.x < 64) g_PART[threadIdx.x] = 0;
    int is64 = detect_is64(e);
    int i = blockIdx.x * 256 + threadIdx.x;
    if (i >= E_TOT) return;
    int d = (i < N_EDGES) ? edge_val(e, is64, N_EDGES + i) : (i - N_EDGES);
    atomicAdd(&g_DEG[d], 1);
}

__global__ __launch_bounds__(1024) void k_scanf() {
    __shared__ int s[1024];
    __shared__ int off_s;
    int i = blockIdx.x * 1024 + threadIdx.x;
    int v = (i < N_NODES) ? g_DEG[i] : 0;
    if (i < N_NODES) g_DEG[i] = 0;
    s[threadIdx.x] = v;
    __syncthreads();
    #pragma unroll
    for (int off = 1; off < 1024; off <<= 1) {
        int t = (threadIdx.x >= off) ? s[threadIdx.x - off] : 0;
        __syncthreads();
        s[threadIdx.x] += t;
        __syncthreads();
    }
    int incl = s[threadIdx.x];
    if (threadIdx.x == 1023)
        atomicExch(&g_PART[blockIdx.x], incl);   // partial >= 848 > 0
    if (threadIdx.x < 32) {
        int sum = 0;
        for (int b = threadIdx.x; b < (int)blockIdx.x; b += 32) {
            int t;
            do { t = atomicAdd(&g_PART[b], 0); } while (t == 0);
            sum += t;
        }
        #pragma unroll
        for (int d = 16; d > 0; d >>= 1)
            sum += __shfl_down_sync(0xFFFFFFFFu, sum, d);
        if (threadIdx.x == 0) off_s = sum;
    }
    __syncthreads();
    if (i < N_NODES) {
        int r = incl - v + off_s;
        g_ROWPTR[i] = r;
        g_CURSOR[i] = r;
    }
    if (i == 0) g_ROWPTR[N_NODES] = E_TOT;
}

__global__ __launch_bounds__(256) void k_scatter(const void* __restrict__ e) {
    int is64 = detect_is64(e);
    int i = blockIdx.x * 256 + threadIdx.x;
    if (i >= E_TOT) return;
    int s_, d_;
    if (i < N_EDGES) {
        s_ = edge_val(e, is64, i);
        d_ = edge_val(e, is64, N_EDGES + i);
    } else {
        s_ = d_ = i - N_EDGES;
    }
    int pos = atomicAdd(&g_CURSOR[d_], 1);
    g_CSR[pos] = s_;
}

// ------------------------- fp16 tensor-core dual GEMM, fp32 out --------------
#define ASP_STRIDE 20
#define WSP_STRIDE 260

__device__ __forceinline__ void mma_f16(float4& d, const unsigned a[4], const unsigned b[2]) {
    asm volatile(
        "mma.sync.aligned.m16n8k16.row.col.f32.f16.f16.f32 "
        "{%0,%1,%2,%3}, {%4,%5,%6,%7}, {%8,%9}, {%0,%1,%2,%3};"
        : "+f"(d.x), "+f"(d.y), "+f"(d.z), "+f"(d.w)
        : "r"(a[0]), "r"(a[1]), "r"(a[2]), "r"(a[3]), "r"(b[0]), "r"(b[1]));
}

__global__ __launch_bounds__(512, 1) void k_gemm_tc(const float* __restrict__ A,
                                                    const float* __restrict__ Wl,
                                                    const float* __restrict__ Wr,
                                                    float* __restrict__ XL,
                                                    float* __restrict__ XR, int M) {
    __shared__ __half2 Asp[128][ASP_STRIDE];
    __shared__ __half2 Wsp[16][WSP_STRIDE];

    int tid = threadIdx.x;
    int wid = tid >> 5, lane = tid & 31;
    int g = lane >> 2, t = lane & 3;
    int wm = wid & 3, wn = wid >> 2;
    int m0 = blockIdx.x * 128;

    float4 C[2][8];
    #pragma unroll
    for (int i = 0; i < 2; i++)
        #pragma unroll
        for (int j = 0; j < 8; j++) C[i][j] = make_float4(0.f, 0.f, 0.f, 0.f);

    for (int k0 = 0; k0 < 128; k0 += 32) {
        #pragma unroll
        for (int j = 0; j < 2; j++) {
            int f = tid + 512 * j;
            int row = f >> 3, colf = (f & 7) * 4;
            float4 v = make_float4(0.f, 0.f, 0.f, 0.f);
            if (m0 + row < M)
                v = *(const float4*)(A + (size_t)(m0 + row) * 128 + k0 + colf);
            int c2 = colf >> 1;
            Asp[row][c2]     = __floats2half2_rn(v.x, v.y);
            Asp[row][c2 + 1] = __floats2half2_rn(v.z, v.w);
        }
        #pragma unroll
        for (int j = 0; j < 2; j++) {
            int f = tid + 512 * j;
            int k2 = f >> 6, nf = (f & 63) * 4;
            int k = k0 + 2 * k2;
            const float* W0 = (nf < 128) ? (Wl + (size_t)k * 128 + nf)
                                         : (Wr + (size_t)k * 128 + (nf - 128));
            const float* W1 = W0 + 128;
            float4 v0 = *(const float4*)W0;
            float4 v1 = *(const float4*)W1;
            Wsp[k2][nf]     = __floats2half2_rn(v0.x, v1.x);
            Wsp[k2][nf + 1] = __floats2half2_rn(v0.y, v1.y);
            Wsp[k2][nf + 2] = __floats2half2_rn(v0.z, v1.z);
            Wsp[k2][nf + 3] = __floats2half2_rn(v0.w, v1.w);
        }
        __syncthreads();

        #pragma unroll
        for (int ks2 = 0; ks2 < 16; ks2 += 8) {
            unsigned a[2][4], b[8][2];
            #pragma unroll
            for (int mt = 0; mt < 2; mt++) {
                int r = wm * 32 + mt * 16;
                a[mt][0] = *(const unsigned*)&Asp[r + g][ks2 + t];
                a[mt][1] = *(const unsigned*)&Asp[r + g + 8][ks2 + t];
                a[mt][2] = *(const unsigned*)&Asp[r + g][ks2 + t + 4];
                a[mt][3] = *(const unsigned*)&Asp[r + g + 8][ks2 + t + 4];
            }
            #pragma unroll
            for (int j = 0; j < 8; j++) {
                int n = wn * 64 + j * 8 + g;
                b[j][0] = *(const unsigned*)&Wsp[ks2 + t][n];
                b[j][1] = *(const unsigned*)&Wsp[ks2 + t + 4][n];
            }
            #pragma unroll
            for (int mt = 0; mt < 2; mt++)
                #pragma unroll
                for (int j = 0; j < 8; j++) mma_f16(C[mt][j], a[mt], b[j]);
        }
        __syncthreads();
    }

    float* base = (wn < 2) ? XL : XR;
    int ncol0 = (wn & 1) * 64;
    #pragma unroll
    for (int mt = 0; mt < 2; mt++) {
        int r0 = m0 + wm * 32 + mt * 16 + g;
        #pragma unroll
        for (int j = 0; j < 8; j++) {
            int c = ncol0 + j * 8 + 2 * t;
            if (r0 < M)
                *(float2*)(base + (size_t)r0 * 128 + c) = make_float2(C[mt][j].x, C[mt][j].y);
            if (r0 + 8 < M)
                *(float2*)(base + (size_t)(r0 + 8) * 128 + c) = make_float2(C[mt][j].z, C[mt][j].w);
        }
    }
}

// ------------------------- GATv2 aggregation (packed f32x2) ------------------
// Warp per dst node, two edges in flight (lanes 0-15 even edge, 16-31 odd).
// Lane owns 8 fp32 channels = 2 float4 loads = 4 packed f32x2 registers.
// logit: a·leaky(v) = (0.6a)·v + (0.4a)·|v| — packed: per pair 1 add2 + 2 fma2
// + abs(2 LOP3, alu pipe). Accumulate: 4 fma2/edge. exp serves 2 edges.
struct P4 { u64 v[4]; };

__device__ __forceinline__ P4 load_p4(const float* __restrict__ p, int hl) {
    float4 lo = __ldg((const float4*)p + 2 * hl);
    float4 hi = __ldg((const float4*)p + 2 * hl + 1);
    P4 r;
    r.v[0] = pk2(lo.x, lo.y);
    r.v[1] = pk2(lo.z, lo.w);
    r.v[2] = pk2(hi.x, hi.y);
    r.v[3] = pk2(hi.z, hi.w);
    return r;
}

__device__ __forceinline__ float logit_p4(const P4& x, const P4& xr,
                                          const P4& a6, const P4& a4) {
    u64 p2a = 0, p2b = 0;   // two chains for ILP; 0 == packed (0.f, 0.f)
    #pragma unroll
    for (int j = 0; j < 4; j += 2) {
        u64 va = add2(x.v[j], xr.v[j]);
        u64 vb = add2(x.v[j + 1], xr.v[j + 1]);
        p2a = fma2(a6.v[j], va, p2a);
        p2b = fma2(a6.v[j + 1], vb, p2b);
        p2a = fma2(a4.v[j], abs2(va), p2a);
        p2b = fma2(a4.v[j + 1], abs2(vb), p2b);
    }
    u64 p2 = add2(p2a, p2b);
    float lo, hi;
    upk2(p2, lo, hi);
    return lo + hi;
}

__global__ __launch_bounds__(256) void k_agg(const float* __restrict__ XL,
                                             const float* __restrict__ XR,
                                             const float* __restrict__ att,
                                             const float* __restrict__ bias,
                                             float* __restrict__ out) {
    int warp = (blockIdx.x * blockDim.x + threadIdx.x) >> 5;
    int lane = threadIdx.x & 31;
    if (warp >= N_NODES) return;
    int half = lane >> 4;
    int hl   = lane & 15;

    P4 a = load_p4(att, hl);
    P4 a6, a4;
    {
        u64 c6 = pk2(0.6f, 0.6f), c4 = pk2(0.4f, 0.4f);
        #pragma unroll
        for (int j = 0; j < 4; j++) {
            a6.v[j] = fma2(a.v[j], c6, 0);
            a4.v[j] = fma2(a.v[j], c4, 0);
        }
    }
    P4 xr = load_p4(XR + (size_t)warp * 128, hl);

    int e0 = __ldg(&g_ROWPTR[warp]);
    int e1 = __ldg(&g_ROWPTR[warp + 1]);

    float s = 0.f;
    P4 acc;
    acc.v[0] = acc.v[1] = acc.v[2] = acc.v[3] = 0;

    int e = e0;
    for (; e + 4 <= e1; e += 4) {
        int s0 = __ldg(&g_CSR[e + half]);
        int s1 = __ldg(&g_CSR[e + 2 + half]);
        P4 x0 = load_p4(XL + (size_t)s0 * 128, hl);
        P4 x1 = load_p4(XL + (size_t)s1 * 128, hl);

        float p0 = logit_p4(x0, xr, a6, a4);
        float p1 = logit_p4(x1, xr, a6, a4);
        p0 += __shfl_xor_sync(0xFFFFFFFFu, p0, 1);
        p1 += __shfl_xor_sync(0xFFFFFFFFu, p1, 1);
        p0 += __shfl_xor_sync(0xFFFFFFFFu, p0, 2);
        p1 += __shfl_xor_sync(0xFFFFFFFFu, p1, 2);
        float w0 = __expf(p0), w1 = __expf(p1);
        s += w0 + w1;

        u64 w02 = pk2(w0, w0), w12 = pk2(w1, w1);
        #pragma unroll
        for (int j = 0; j < 4; j++) {
            acc.v[j] = fma2(w02, x0.v[j], acc.v[j]);
            acc.v[j] = fma2(w12, x1.v[j], acc.v[j]);
        }
    }
    for (; e < e1; e += 2) {
        int ei = e + half;
        bool valid = ei < e1;
        int src = __ldg(&g_CSR[valid ? ei : e]);
        P4 x = load_p4(XL + (size_t)src * 128, hl);
        float p = logit_p4(x, xr, a6, a4);
        p += __shfl_xor_sync(0xFFFFFFFFu, p, 1);
        p += __shfl_xor_sync(0xFFFFFFFFu, p, 2);
        float w = valid ? __expf(p) : 0.f;
        s += w;
        u64 w2 = pk2(w, w);
        #pragma unroll
        for (int j = 0; j < 4; j++)
            acc.v[j] = fma2(w2, x.v[j], acc.v[j]);
    }

    // merge halves: s total to all lanes; acc channels to their owner half.
    s += __shfl_xor_sync(0xFFFFFFFFu, s, 16);
    float af[8];
    #pragma unroll
    for (int j = 0; j < 4; j++) upk2(acc.v[j], af[2 * j], af[2 * j + 1]);
    #pragma unroll
    for (int c = 0; c < 8; c++)
        af[c] += __shfl_xor_sync(0xFFFFFFFFu, af[c], 16);

    float inv = 1.f / (s + 1e-16f);
    // lane writes its own 8 channels (fp32), split as two float4 stores
    const float4* bp = (const float4*)bias;
    float4 b0 = __ldg(bp + 2 * hl), b1 = __ldg(bp + 2 * hl + 1);
    float4 o0, o1;
    o0.x = fmaxf(af[0] * inv + b0.x, 0.f);
    o0.y = fmaxf(af[1] * inv + b0.y, 0.f);
    o0.z = fmaxf(af[2] * inv + b0.z, 0.f);
    o0.w = fmaxf(af[3] * inv + b0.w, 0.f);
    o1.x = fmaxf(af[4] * inv + b1.x, 0.f);
    o1.y = fmaxf(af[5] * inv + b1.y, 0.f);
    o1.z = fmaxf(af[6] * inv + b1.z, 0.f);
    o1.w = fmaxf(af[7] * inv + b1.w, 0.f);
    // halves hold identical merged values; let half 0 write to avoid dup traffic
    if (half == 0) {
        float4* op = (float4*)(out + (size_t)warp * 128);
        op[2 * hl]     = o0;
        op[2 * hl + 1] = o1;
    }
}

// ------------------------- launch --------------------------------------------
extern "C" void kernel_launch(void* const* d_in, const int* in_sizes, int n_in,
                              void* d_out, int out_size) {
    const float* x    = (const float*)d_in[0];
    const void*  ei   = d_in[1];
    const float* W1l  = (const float*)d_in[2];
    const float* W1r  = (const float*)d_in[3];
    const float* att1 = (const float*)d_in[4];
    const float* b1   = (const float*)d_in[5];
    const float* W2l  = (const float*)d_in[6];
    const float* W2r  = (const float*)d_in[7];
    const float* att2 = (const float*)d_in[8];
    const float* b2   = (const float*)d_in[9];
    float* out = (float*)d_out;

    float *XL, *XR, *H1;
    cudaGetSymbolAddress((void**)&XL, g_XL);
    cudaGetSymbolAddress((void**)&XR, g_XR);
    cudaGetSymbolAddress((void**)&H1, g_H1);

    static cudaStream_t s1 = nullptr;
    static cudaEvent_t evFork = nullptr, evG1 = nullptr;
    if (!s1) {
        cudaStreamCreateWithFlags(&s1, cudaStreamNonBlocking);
        cudaEventCreateWithFlags(&evFork, cudaEventDisableTiming);
        cudaEventCreateWithFlags(&evG1, cudaEventDisableTiming);
    }

    int gemm_grid = (N_NODES + 127) / 128;
    int agg_grid  = (N_NODES * 32 + 255) / 256;
    int nblk = (N_NODES + 1023) / 1024;

    // fork: layer-1 GEMM on side stream, concurrent with CSR build
    cudaEventRecord(evFork, 0);
    cudaStreamWaitEvent(s1, evFork, 0);
    k_gemm_tc<<<gemm_grid, 512, 0, s1>>>(x, W1l, W1r, XL, XR, N_NODES);
    cudaEventRecord(evG1, s1);

    // CSR build on main stream (R8 3-kernel chain)
    k_hist<<<(E_TOT + 255) / 256, 256>>>(ei);
    k_scanf<<<nblk, 1024>>>();
    k_scatter<<<(E_TOT + 255) / 256, 256>>>(ei);

    // join
    cudaStreamWaitEvent(0, evG1, 0);

    // layer 1 aggregate
    k_agg<<<agg_grid, 256>>>(XL, XR, att1, b1, H1);

    // layer 2
    k_gemm_tc<<<gemm_grid, 512>>>(H1, W2l, W2r, XL, XR, N_NODES);
    k_agg<<<agg_grid, 256>>>(XL, XR, att2, b2, out);
}

// round 12
// speedup vs baseline: 1.0469x; 1.0469x over previous
#include <cuda_runtime.h>
#include <cuda_fp16.h>
#include <math.h>
#include <stdint.h>

#define N_NODES 50000
#define N_EDGES 1600000
#define E_TOT   (N_EDGES + N_NODES)
#define HID     128
#define SLOPE   0.2f

// ------------------------- device scratch (no allocs allowed) ---------------
__device__ __half g_XLh[(size_t)N_NODES * HID];
__device__ __half g_XRh[(size_t)N_NODES * HID];
__device__ float  g_H1[(size_t)N_NODES * HID];
__device__ int    g_DEG[N_NODES];       // zero-init; k_scanf re-zeroes
__device__ int    g_ROWPTR[N_NODES + 1];
__device__ int    g_RANK[E_TOT];        // per-edge rank within its dst bucket
__device__ int    g_CSR[E_TOT];
__device__ int    g_PART[64];           // zeroed by k_hist block 0

// ------------------------- edge dtype helpers --------------------------------
__device__ __forceinline__ int detect_is64(const void* e) {
    int flag = (((const int*)e)[2 * threadIdx.x + 1] != 0);
    return !__syncthreads_or(flag);
}
__device__ __forceinline__ int edge_val(const void* e, int is64, int idx) {
    return is64 ? (int)((const long long*)e)[idx] : ((const int*)e)[idx];
}

// ------------------------- CSR build -----------------------------------------
// hist: atomicAdd returns the edge's rank within its dst bucket -> store it.
__global__ __launch_bounds__(256) void k_hist(const void* __restrict__ e) {
    if (blockIdx.x == 0 && threadIdx.x < 64) g_PART[threadIdx.x] = 0;
    int is64 = detect_is64(e);
    int i = blockIdx.x * 256 + threadIdx.x;
    if (i >= E_TOT) return;
    int d = (i < N_EDGES) ? edge_val(e, is64, N_EDGES + i) : (i - N_EDGES);
    g_RANK[i] = atomicAdd(&g_DEG[d], 1);
}

__global__ __launch_bounds__(1024) void k_scanf() {
    __shared__ int s[1024];
    __shared__ int off_s;
    int i = blockIdx.x * 1024 + threadIdx.x;
    int v = (i < N_NODES) ? g_DEG[i] : 0;
    if (i < N_NODES) g_DEG[i] = 0;
    s[threadIdx.x] = v;
    __syncthreads();
    #pragma unroll
    for (int off = 1; off < 1024; off <<= 1) {
        int t = (threadIdx.x >= off) ? s[threadIdx.x - off] : 0;
        __syncthreads();
        s[threadIdx.x] += t;
        __syncthreads();
    }
    int incl = s[threadIdx.x];
    if (threadIdx.x == 1023)
        atomicExch(&g_PART[blockIdx.x], incl);   // partial >= 848 > 0
    if (threadIdx.x < 32) {
        int sum = 0;
        for (int b = threadIdx.x; b < (int)blockIdx.x; b += 32) {
            int t;
            do { t = atomicAdd(&g_PART[b], 0); } while (t == 0);
            sum += t;
        }
        #pragma unroll
        for (int d = 16; d > 0; d >>= 1)
            sum += __shfl_down_sync(0xFFFFFFFFu, sum, d);
        if (threadIdx.x == 0) off_s = sum;
    }
    __syncthreads();
    if (i < N_NODES)
        g_ROWPTR[i] = incl - v + off_s;
    if (i == 0) g_ROWPTR[N_NODES] = E_TOT;
}

// scatter: atomic-free — pos = ROWPTR[dst] + RANK[i]
__global__ __launch_bounds__(256) void k_scatter(const void* __restrict__ e) {
    int is64 = detect_is64(e);
    int i = blockIdx.x * 256 + threadIdx.x;
    if (i >= E_TOT) return;
    int s_, d_;
    if (i < N_EDGES) {
        s_ = edge_val(e, is64, i);
        d_ = edge_val(e, is64, N_EDGES + i);
    } else {
        s_ = d_ = i - N_EDGES;
    }
    int pos = __ldg(&g_ROWPTR[d_]) + __ldg(&g_RANK[i]);
    g_CSR[pos] = s_;
}

// ------------------------- fp16 tensor-core dual GEMM ------------------------
#define ASP_STRIDE 20
#define WSP_STRIDE 260

__device__ __forceinline__ void mma_f16(float4& d, const unsigned a[4], const unsigned b[2]) {
    asm volatile(
        "mma.sync.aligned.m16n8k16.row.col.f32.f16.f16.f32 "
        "{%0,%1,%2,%3}, {%4,%5,%6,%7}, {%8,%9}, {%0,%1,%2,%3};"
        : "+f"(d.x), "+f"(d.y), "+f"(d.z), "+f"(d.w)
        : "r"(a[0]), "r"(a[1]), "r"(a[2]), "r"(a[3]), "r"(b[0]), "r"(b[1]));
}

__global__ __launch_bounds__(512, 1) void k_gemm_tc(const float* __restrict__ A,
                                                    const float* __restrict__ Wl,
                                                    const float* __restrict__ Wr,
                                                    __half* __restrict__ XL,
                                                    __half* __restrict__ XR, int M) {
    __shared__ __half2 Asp[128][ASP_STRIDE];
    __shared__ __half2 Wsp[16][WSP_STRIDE];

    int tid = threadIdx.x;
    int wid = tid >> 5, lane = tid & 31;
    int g = lane >> 2, t = lane & 3;
    int wm = wid & 3, wn = wid >> 2;
    int m0 = blockIdx.x * 128;

    float4 C[2][8];
    #pragma unroll
    for (int i = 0; i < 2; i++)
        #pragma unroll
        for (int j = 0; j < 8; j++) C[i][j] = make_float4(0.f, 0.f, 0.f, 0.f);

    for (int k0 = 0; k0 < 128; k0 += 32) {
        #pragma unroll
        for (int j = 0; j < 2; j++) {
            int f = tid + 512 * j;
            int row = f >> 3, colf = (f & 7) * 4;
            float4 v = make_float4(0.f, 0.f, 0.f, 0.f);
            if (m0 + row < M)
                v = *(const float4*)(A + (size_t)(m0 + row) * 128 + k0 + colf);
            int c2 = colf >> 1;
            Asp[row][c2]     = __floats2half2_rn(v.x, v.y);
            Asp[row][c2 + 1] = __floats2half2_rn(v.z, v.w);
        }
        #pragma unroll
        for (int j = 0; j < 2; j++) {
            int f = tid + 512 * j;
            int k2 = f >> 6, nf = (f & 63) * 4;
            int k = k0 + 2 * k2;
            const float* W0 = (nf < 128) ? (Wl + (size_t)k * 128 + nf)
                                         : (Wr + (size_t)k * 128 + (nf - 128));
            const float* W1 = W0 + 128;
            float4 v0 = *(const float4*)W0;
            float4 v1 = *(const float4*)W1;
            Wsp[k2][nf]     = __floats2half2_rn(v0.x, v1.x);
            Wsp[k2][nf + 1] = __floats2half2_rn(v0.y, v1.y);
            Wsp[k2][nf + 2] = __floats2half2_rn(v0.z, v1.z);
            Wsp[k2][nf + 3] = __floats2half2_rn(v0.w, v1.w);
        }
        __syncthreads();

        #pragma unroll
        for (int ks2 = 0; ks2 < 16; ks2 += 8) {
            unsigned a[2][4], b[8][2];
            #pragma unroll
            for (int mt = 0; mt < 2; mt++) {
                int r = wm * 32 + mt * 16;
                a[mt][0] = *(const unsigned*)&Asp[r + g][ks2 + t];
                a[mt][1] = *(const unsigned*)&Asp[r + g + 8][ks2 + t];
                a[mt][2] = *(const unsigned*)&Asp[r + g][ks2 + t + 4];
                a[mt][3] = *(const unsigned*)&Asp[r + g + 8][ks2 + t + 4];
            }
            #pragma unroll
            for (int j = 0; j < 8; j++) {
                int n = wn * 64 + j * 8 + g;
                b[j][0] = *(const unsigned*)&Wsp[ks2 + t][n];
                b[j][1] = *(const unsigned*)&Wsp[ks2 + t + 4][n];
            }
            #pragma unroll
            for (int mt = 0; mt < 2; mt++)
                #pragma unroll
                for (int j = 0; j < 8; j++) mma_f16(C[mt][j], a[mt], b[j]);
        }
        __syncthreads();
    }

    __half* base = (wn < 2) ? XL : XR;
    int ncol0 = (wn & 1) * 64;
    #pragma unroll
    for (int mt = 0; mt < 2; mt++) {
        int r0 = m0 + wm * 32 + mt * 16 + g;
        #pragma unroll
        for (int j = 0; j < 8; j++) {
            int c = ncol0 + j * 8 + 2 * t;
            if (r0 < M)
                *(__half2*)(base + (size_t)r0 * 128 + c) = __floats2half2_rn(C[mt][j].x, C[mt][j].y);
            if (r0 + 8 < M)
                *(__half2*)(base + (size_t)(r0 + 8) * 128 + c) = __floats2half2_rn(C[mt][j].z, C[mt][j].w);
        }
    }
}

// ------------------------- GATv2 aggregation ---------------------------------
// Warp per dst node, two edges in flight (lanes 0-15 even edge, 16-31 odd).
// fp16 gathers: lane loads ONE uint4 (its 8 channels). 2-edge loop steps keep
// live registers low; __launch_bounds__(256,5) caps regs for 62.5% occupancy.
__device__ __forceinline__ void unp16(uint4 u, float4& A, float4& B) {
    float2 f0 = __half22float2(*reinterpret_cast<__half2*>(&u.x));
    float2 f1 = __half22float2(*reinterpret_cast<__half2*>(&u.y));
    float2 f2 = __half22float2(*reinterpret_cast<__half2*>(&u.z));
    float2 f3 = __half22float2(*reinterpret_cast<__half2*>(&u.w));
    A = make_float4(f0.x, f0.y, f1.x, f1.y);
    B = make_float4(f2.x, f2.y, f3.x, f3.y);
}

__device__ __forceinline__ float logit8(const float4& xA, const float4& xB,
                                        const float4& xrA, const float4& xrB,
                                        const float4& a6A, const float4& a4A,
                                        const float4& a6B, const float4& a4B) {
    float vx = xA.x + xrA.x, vy = xA.y + xrA.y, vz = xA.z + xrA.z, vw = xA.w + xrA.w;
    float p = a6A.x * vx + a4A.x * fabsf(vx);
    p = fmaf(a6A.y, vy, fmaf(a4A.y, fabsf(vy), p));
    p = fmaf(a6A.z, vz, fmaf(a4A.z, fabsf(vz), p));
    p = fmaf(a6A.w, vw, fmaf(a4A.w, fabsf(vw), p));
    vx = xB.x + xrB.x; vy = xB.y + xrB.y; vz = xB.z + xrB.z; vw = xB.w + xrB.w;
    p = fmaf(a6B.x, vx, fmaf(a4B.x, fabsf(vx), p));
    p = fmaf(a6B.y, vy, fmaf(a4B.y, fabsf(vy), p));
    p = fmaf(a6B.z, vz, fmaf(a4B.z, fabsf(vz), p));
    p = fmaf(a6B.w, vw, fmaf(a4B.w, fabsf(vw), p));
    return p;
}

__global__ __launch_bounds__(256, 5) void k_agg(const __half* __restrict__ XL,
                                                const __half* __restrict__ XR,
                                                const float* __restrict__ att,
                                                const float* __restrict__ bias,
                                                float* __restrict__ out) {
    int warp = (blockIdx.x * blockDim.x + threadIdx.x) >> 5;
    int lane = threadIdx.x & 31;
    if (warp >= N_NODES) return;
    int half = lane >> 4;
    int hl   = lane & 15;

    const float4* attp = (const float4*)att;
    float4 aA = __ldg(attp + 2 * hl), aB = __ldg(attp + 2 * hl + 1);
    float4 a6A = make_float4(0.6f * aA.x, 0.6f * aA.y, 0.6f * aA.z, 0.6f * aA.w);
    float4 a4A = make_float4(0.4f * aA.x, 0.4f * aA.y, 0.4f * aA.z, 0.4f * aA.w);
    float4 a6B = make_float4(0.6f * aB.x, 0.6f * aB.y, 0.6f * aB.z, 0.6f * aB.w);
    float4 a4B = make_float4(0.4f * aB.x, 0.4f * aB.y, 0.4f * aB.z, 0.4f * aB.w);

    uint4 xru = __ldg((const uint4*)(XR + (size_t)warp * 128) + hl);
    float4 xrA, xrB;
    unp16(xru, xrA, xrB);

    int e0 = __ldg(&g_ROWPTR[warp]);
    int e1 = __ldg(&g_ROWPTR[warp + 1]);

    float s = 0.f;
    float4 accA = make_float4(0.f, 0.f, 0.f, 0.f);
    float4 accB = make_float4(0.f, 0.f, 0.f, 0.f);

    int e = e0;
    for (; e + 2 <= e1; e += 2) {
        int src = __ldg(&g_CSR[e + half]);
        uint4 u = __ldg((const uint4*)(XL + (size_t)src * 128) + hl);
        float4 xA, xB;
        unp16(u, xA, xB);
        float p = logit8(xA, xB, xrA, xrB, a6A, a4A, a6B, a4B);
        p += __shfl_xor_sync(0xFFFFFFFFu, p, 1);
        p += __shfl_xor_sync(0xFFFFFFFFu, p, 2);
        float w = __expf(p);
        s += w;
        accA.x += w * xA.x; accA.y += w * xA.y;
        accA.z += w * xA.z; accA.w += w * xA.w;
        accB.x += w * xB.x; accB.y += w * xB.y;
        accB.z += w * xB.z; accB.w += w * xB.w;
    }
    if (e < e1) {               // one leftover edge: half 0 valid, half 1 masked
        int src = __ldg(&g_CSR[e]);
        uint4 u = __ldg((const uint4*)(XL + (size_t)src * 128) + hl);
        float4 xA, xB;
        unp16(u, xA, xB);
        float p = logit8(xA, xB, xrA, xrB, a6A, a4A, a6B, a4B);
        p += __shfl_xor_sync(0xFFFFFFFFu, p, 1);
        p += __shfl_xor_sync(0xFFFFFFFFu, p, 2);
        float w = (half == 0) ? __expf(p) : 0.f;
        s += w;
        accA.x += w * xA.x; accA.y += w * xA.y;
        accA.z += w * xA.z; accA.w += w * xA.w;
        accB.x += w * xB.x; accB.y += w * xB.y;
        accB.z += w * xB.z; accB.w += w * xB.w;
    }

    s += __shfl_xor_sync(0xFFFFFFFFu, s, 16);
    accA.x += __shfl_down_sync(0xFFFFFFFFu, accA.x, 16);
    accA.y += __shfl_down_sync(0xFFFFFFFFu, accA.y, 16);
    accA.z += __shfl_down_sync(0xFFFFFFFFu, accA.z, 16);
    accA.w += __shfl_down_sync(0xFFFFFFFFu, accA.w, 16);
    accB.x += __shfl_up_sync(0xFFFFFFFFu, accB.x, 16);
    accB.y += __shfl_up_sync(0xFFFFFFFFu, accB.y, 16);
    accB.z += __shfl_up_sync(0xFFFFFFFFu, accB.z, 16);
    accB.w += __shfl_up_sync(0xFFFFFFFFu, accB.w, 16);

    float inv = 1.f / (s + 1e-16f);
    float4 acc = half ? accB : accA;
    float4 b4 = __ldg((const float4*)bias + 2 * hl + half);
    float4 o;
    o.x = fmaxf(acc.x * inv + b4.x, 0.f);
    o.y = fmaxf(acc.y * inv + b4.y, 0.f);
    o.z = fmaxf(acc.z * inv + b4.z, 0.f);
    o.w = fmaxf(acc.w * inv + b4.w, 0.f);
    *((float4*)(out + (size_t)warp * 128) + 2 * hl + half) = o;
}

// ------------------------- launch --------------------------------------------
extern "C" void kernel_launch(void* const* d_in, const int* in_sizes, int n_in,
                              void* d_out, int out_size) {
    const float* x    = (const float*)d_in[0];
    const void*  ei   = d_in[1];
    const float* W1l  = (const float*)d_in[2];
    const float* W1r  = (const float*)d_in[3];
    const float* att1 = (const float*)d_in[4];
    const float* b1   = (const float*)d_in[5];
    const float* W2l  = (const float*)d_in[6];
    const float* W2r  = (const float*)d_in[7];
    const float* att2 = (const float*)d_in[8];
    const float* b2   = (const float*)d_in[9];
    float* out = (float*)d_out;

    __half *XL, *XR;
    float *H1;
    cudaGetSymbolAddress((void**)&XL, g_XLh);
    cudaGetSymbolAddress((void**)&XR, g_XRh);
    cudaGetSymbolAddress((void**)&H1, g_H1);

    static cudaStream_t s1 = nullptr;
    static cudaEvent_t evFork = nullptr, evG1 = nullptr;
    if (!s1) {
        cudaStreamCreateWithFlags(&s1, cudaStreamNonBlocking);
        cudaEventCreateWithFlags(&evFork, cudaEventDisableTiming);
        cudaEventCreateWithFlags(&evG1, cudaEventDisableTiming);
    }

    int gemm_grid = (N_NODES + 127) / 128;
    int agg_grid  = (N_NODES * 32 + 255) / 256;
    int nblk = (N_NODES + 1023) / 1024;

    // fork: layer-1 GEMM on side stream, concurrent with CSR build
    cudaEventRecord(evFork, 0);
    cudaStreamWaitEvent(s1, evFork, 0);
    k_gemm_tc<<<gemm_grid, 512, 0, s1>>>(x, W1l, W1r, XL, XR, N_NODES);
    cudaEventRecord(evG1, s1);

    // CSR build on main stream
    k_hist<<<(E_TOT + 255) / 256, 256>>>(ei);
    k_scanf<<<nblk, 1024>>>();
    k_scatter<<<(E_TOT + 255) / 256, 256>>>(ei);

    // join
    cudaStreamWaitEvent(0, evG1, 0);

    // layer 1 aggregate
    k_agg<<<agg_grid, 256>>>(XL, XR, att1, b1, H1);

    // layer 2
    k_gemm_tc<<<gemm_grid, 512>>>(H1, W2l, W2r, XL, XR, N_NODES);
    k_agg<<<agg_grid, 256>>>(XL, XR, att2, b2, out);
}

// round 13
// speedup vs baseline: 1.1235x; 1.0731x over previous
#include <cuda_runtime.h>
#include <cuda_fp16.h>
#include <math.h>
#include <stdint.h>

#define N_NODES 50000
#define N_EDGES 1600000
#define E_TOT   (N_EDGES + N_NODES)
#define HID     128
#define SLOPE   0.2f

// ------------------------- device scratch (no allocs allowed) ---------------
__device__ __half g_XLh[(size_t)N_NODES * HID];
__device__ __half g_XRh[(size_t)N_NODES * HID];
__device__ float  g_H1[(size_t)N_NODES * HID];
__device__ int    g_DEG[N_NODES];       // zero-init; k_scanf re-zeroes
__device__ int    g_ROWPTR[N_NODES + 1];
__device__ int    g_RANK[E_TOT];        // per-edge rank within its dst bucket
__device__ int    g_CSR[E_TOT];
__device__ int    g_PART[64];           // zeroed by k_hist block 0

// ------------------------- edge dtype helpers --------------------------------
__device__ __forceinline__ int detect_is64(const void* e) {
    int flag = (((const int*)e)[2 * threadIdx.x + 1] != 0);
    return !__syncthreads_or(flag);
}
__device__ __forceinline__ int edge_val(const void* e, int is64, int idx) {
    return is64 ? (int)((const long long*)e)[idx] : ((const int*)e)[idx];
}

// ------------------------- CSR build -----------------------------------------
// hist: atomicAdd returns the edge's rank within its dst bucket -> store it.
__global__ __launch_bounds__(256) void k_hist(const void* __restrict__ e) {
    if (blockIdx.x == 0 && threadIdx.x < 64) g_PART[threadIdx.x] = 0;
    int is64 = detect_is64(e);
    int i = blockIdx.x * 256 + threadIdx.x;
    if (i >= E_TOT) return;
    int d = (i < N_EDGES) ? edge_val(e, is64, N_EDGES + i) : (i - N_EDGES);
    g_RANK[i] = atomicAdd(&g_DEG[d], 1);
}

__global__ __launch_bounds__(1024) void k_scanf() {
    __shared__ int s[1024];
    __shared__ int off_s;
    int i = blockIdx.x * 1024 + threadIdx.x;
    int v = (i < N_NODES) ? g_DEG[i] : 0;
    if (i < N_NODES) g_DEG[i] = 0;
    s[threadIdx.x] = v;
    __syncthreads();
    #pragma unroll
    for (int off = 1; off < 1024; off <<= 1) {
        int t = (threadIdx.x >= off) ? s[threadIdx.x - off] : 0;
        __syncthreads();
        s[threadIdx.x] += t;
        __syncthreads();
    }
    int incl = s[threadIdx.x];
    if (threadIdx.x == 1023)
        atomicExch(&g_PART[blockIdx.x], incl);   // partial >= 848 > 0
    if (threadIdx.x < 32) {
        int sum = 0;
        for (int b = threadIdx.x; b < (int)blockIdx.x; b += 32) {
            int t;
            do { t = atomicAdd(&g_PART[b], 0); } while (t == 0);
            sum += t;
        }
        #pragma unroll
        for (int d = 16; d > 0; d >>= 1)
            sum += __shfl_down_sync(0xFFFFFFFFu, sum, d);
        if (threadIdx.x == 0) off_s = sum;
    }
    __syncthreads();
    if (i < N_NODES)
        g_ROWPTR[i] = incl - v + off_s;
    if (i == 0) g_ROWPTR[N_NODES] = E_TOT;
}

// scatter: atomic-free — pos = ROWPTR[dst] + RANK[i]
__global__ __launch_bounds__(256) void k_scatter(const void* __restrict__ e) {
    int is64 = detect_is64(e);
    int i = blockIdx.x * 256 + threadIdx.x;
    if (i >= E_TOT) return;
    int s_, d_;
    if (i < N_EDGES) {
        s_ = edge_val(e, is64, i);
        d_ = edge_val(e, is64, N_EDGES + i);
    } else {
        s_ = d_ = i - N_EDGES;
    }
    int pos = __ldg(&g_ROWPTR[d_]) + __ldg(&g_RANK[i]);
    g_CSR[pos] = s_;
}

// ------------------------- fp16 tensor-core dual GEMM ------------------------
#define ASP_STRIDE 20
#define WSP_STRIDE 260

__device__ __forceinline__ void mma_f16(float4& d, const unsigned a[4], const unsigned b[2]) {
    asm volatile(
        "mma.sync.aligned.m16n8k16.row.col.f32.f16.f16.f32 "
        "{%0,%1,%2,%3}, {%4,%5,%6,%7}, {%8,%9}, {%0,%1,%2,%3};"
        : "+f"(d.x), "+f"(d.y), "+f"(d.z), "+f"(d.w)
        : "r"(a[0]), "r"(a[1]), "r"(a[2]), "r"(a[3]), "r"(b[0]), "r"(b[1]));
}

__global__ __launch_bounds__(512, 1) void k_gemm_tc(const float* __restrict__ A,
                                                    const float* __restrict__ Wl,
                                                    const float* __restrict__ Wr,
                                                    __half* __restrict__ XL,
                                                    __half* __restrict__ XR, int M) {
    __shared__ __half2 Asp[128][ASP_STRIDE];
    __shared__ __half2 Wsp[16][WSP_STRIDE];

    int tid = threadIdx.x;
    int wid = tid >> 5, lane = tid & 31;
    int g = lane >> 2, t = lane & 3;
    int wm = wid & 3, wn = wid >> 2;
    int m0 = blockIdx.x * 128;

    float4 C[2][8];
    #pragma unroll
    for (int i = 0; i < 2; i++)
        #pragma unroll
        for (int j = 0; j < 8; j++) C[i][j] = make_float4(0.f, 0.f, 0.f, 0.f);

    for (int k0 = 0; k0 < 128; k0 += 32) {
        #pragma unroll
        for (int j = 0; j < 2; j++) {
            int f = tid + 512 * j;
            int row = f >> 3, colf = (f & 7) * 4;
            float4 v = make_float4(0.f, 0.f, 0.f, 0.f);
            if (m0 + row < M)
                v = *(const float4*)(A + (size_t)(m0 + row) * 128 + k0 + colf);
            int c2 = colf >> 1;
            Asp[row][c2]     = __floats2half2_rn(v.x, v.y);
            Asp[row][c2 + 1] = __floats2half2_rn(v.z, v.w);
        }
        #pragma unroll
        for (int j = 0; j < 2; j++) {
            int f = tid + 512 * j;
            int k2 = f >> 6, nf = (f & 63) * 4;
            int k = k0 + 2 * k2;
            const float* W0 = (nf < 128) ? (Wl + (size_t)k * 128 + nf)
                                         : (Wr + (size_t)k * 128 + (nf - 128));
            const float* W1 = W0 + 128;
            float4 v0 = *(const float4*)W0;
            float4 v1 = *(const float4*)W1;
            Wsp[k2][nf]     = __floats2half2_rn(v0.x, v1.x);
            Wsp[k2][nf + 1] = __floats2half2_rn(v0.y, v1.y);
            Wsp[k2][nf + 2] = __floats2half2_rn(v0.z, v1.z);
            Wsp[k2][nf + 3] = __floats2half2_rn(v0.w, v1.w);
        }
        __syncthreads();

        #pragma unroll
        for (int ks2 = 0; ks2 < 16; ks2 += 8) {
            unsigned a[2][4], b[8][2];
            #pragma unroll
            for (int mt = 0; mt < 2; mt++) {
                int r = wm * 32 + mt * 16;
                a[mt][0] = *(const unsigned*)&Asp[r + g][ks2 + t];
                a[mt][1] = *(const unsigned*)&Asp[r + g + 8][ks2 + t];
                a[mt][2] = *(const unsigned*)&Asp[r + g][ks2 + t + 4];
                a[mt][3] = *(const unsigned*)&Asp[r + g + 8][ks2 + t + 4];
            }
            #pragma unroll
            for (int j = 0; j < 8; j++) {
                int n = wn * 64 + j * 8 + g;
                b[j][0] = *(const unsigned*)&Wsp[ks2 + t][n];
                b[j][1] = *(const unsigned*)&Wsp[ks2 + t + 4][n];
            }
            #pragma unroll
            for (int mt = 0; mt < 2; mt++)
                #pragma unroll
                for (int j = 0; j < 8; j++) mma_f16(C[mt][j], a[mt], b[j]);
        }
        __syncthreads();
    }

    __half* base = (wn < 2) ? XL : XR;
    int ncol0 = (wn & 1) * 64;
    #pragma unroll
    for (int mt = 0; mt < 2; mt++) {
        int r0 = m0 + wm * 32 + mt * 16 + g;
        #pragma unroll
        for (int j = 0; j < 8; j++) {
            int c = ncol0 + j * 8 + 2 * t;
            if (r0 < M)
                *(__half2*)(base + (size_t)r0 * 128 + c) = __floats2half2_rn(C[mt][j].x, C[mt][j].y);
            if (r0 + 8 < M)
                *(__half2*)(base + (size_t)(r0 + 8) * 128 + c) = __floats2half2_rn(C[mt][j].z, C[mt][j].w);
        }
    }
}

// ------------------------- GATv2 aggregation (R8 exact form) -----------------
// Warp per dst node, two edges in flight per half-warp (lanes 0-15 even edge,
// 16-31 odd), 4-edge main loop -> 2 independent row gathers in flight.
__device__ __forceinline__ void unp16(uint4 u, float4& A, float4& B) {
    float2 f0 = __half22float2(*reinterpret_cast<__half2*>(&u.x));
    float2 f1 = __half22float2(*reinterpret_cast<__half2*>(&u.y));
    float2 f2 = __half22float2(*reinterpret_cast<__half2*>(&u.z));
    float2 f3 = __half22float2(*reinterpret_cast<__half2*>(&u.w));
    A = make_float4(f0.x, f0.y, f1.x, f1.y);
    B = make_float4(f2.x, f2.y, f3.x, f3.y);
}

__device__ __forceinline__ float logit8(const float4& xA, const float4& xB,
                                        const float4& xrA, const float4& xrB,
                                        const float4& a6A, const float4& a4A,
                                        const float4& a6B, const float4& a4B) {
    float vx = xA.x + xrA.x, vy = xA.y + xrA.y, vz = xA.z + xrA.z, vw = xA.w + xrA.w;
    float p = a6A.x * vx + a4A.x * fabsf(vx);
    p = fmaf(a6A.y, vy, fmaf(a4A.y, fabsf(vy), p));
    p = fmaf(a6A.z, vz, fmaf(a4A.z, fabsf(vz), p));
    p = fmaf(a6A.w, vw, fmaf(a4A.w, fabsf(vw), p));
    vx = xB.x + xrB.x; vy = xB.y + xrB.y; vz = xB.z + xrB.z; vw = xB.w + xrB.w;
    p = fmaf(a6B.x, vx, fmaf(a4B.x, fabsf(vx), p));
    p = fmaf(a6B.y, vy, fmaf(a4B.y, fabsf(vy), p));
    p = fmaf(a6B.z, vz, fmaf(a4B.z, fabsf(vz), p));
    p = fmaf(a6B.w, vw, fmaf(a4B.w, fabsf(vw), p));
    return p;
}

__global__ __launch_bounds__(256) void k_agg(const __half* __restrict__ XL,
                                             const __half* __restrict__ XR,
                                             const float* __restrict__ att,
                                             const float* __restrict__ bias,
                                             float* __restrict__ out) {
    int warp = (blockIdx.x * blockDim.x + threadIdx.x) >> 5;
    int lane = threadIdx.x & 31;
    if (warp >= N_NODES) return;
    int half = lane >> 4;
    int hl   = lane & 15;

    const float4* attp = (const float4*)att;
    float4 aA = __ldg(attp + 2 * hl), aB = __ldg(attp + 2 * hl + 1);
    float4 a6A = make_float4(0.6f * aA.x, 0.6f * aA.y, 0.6f * aA.z, 0.6f * aA.w);
    float4 a4A = make_float4(0.4f * aA.x, 0.4f * aA.y, 0.4f * aA.z, 0.4f * aA.w);
    float4 a6B = make_float4(0.6f * aB.x, 0.6f * aB.y, 0.6f * aB.z, 0.6f * aB.w);
    float4 a4B = make_float4(0.4f * aB.x, 0.4f * aB.y, 0.4f * aB.z, 0.4f * aB.w);

    uint4 xru = __ldg((const uint4*)(XR + (size_t)warp * 128) + hl);
    float4 xrA, xrB;
    unp16(xru, xrA, xrB);

    int e0 = __ldg(&g_ROWPTR[warp]);
    int e1 = __ldg(&g_ROWPTR[warp + 1]);

    float s = 0.f;
    float4 accA = make_float4(0.f, 0.f, 0.f, 0.f);
    float4 accB = make_float4(0.f, 0.f, 0.f, 0.f);

    int e = e0;
    for (; e + 4 <= e1; e += 4) {
        int s0 = __ldg(&g_CSR[e + half]);
        int s1 = __ldg(&g_CSR[e + 2 + half]);
        uint4 u0 = __ldg((const uint4*)(XL + (size_t)s0 * 128) + hl);
        uint4 u1 = __ldg((const uint4*)(XL + (size_t)s1 * 128) + hl);
        float4 x0A, x0B, x1A, x1B;
        unp16(u0, x0A, x0B);
        unp16(u1, x1A, x1B);

        float p0 = logit8(x0A, x0B, xrA, xrB, a6A, a4A, a6B, a4B);
        float p1 = logit8(x1A, x1B, xrA, xrB, a6A, a4A, a6B, a4B);
        p0 += __shfl_xor_sync(0xFFFFFFFFu, p0, 1);
        p1 += __shfl_xor_sync(0xFFFFFFFFu, p1, 1);
        p0 += __shfl_xor_sync(0xFFFFFFFFu, p0, 2);
        p1 += __shfl_xor_sync(0xFFFFFFFFu, p1, 2);
        float w0 = __expf(p0), w1 = __expf(p1);

        s += w0 + w1;
        accA.x += w0 * x0A.x + w1 * x1A.x;
        accA.y += w0 * x0A.y + w1 * x1A.y;
        accA.z += w0 * x0A.z + w1 * x1A.z;
        accA.w += w0 * x0A.w + w1 * x1A.w;
        accB.x += w0 * x0B.x + w1 * x1B.x;
        accB.y += w0 * x0B.y + w1 * x1B.y;
        accB.z += w0 * x0B.z + w1 * x1B.z;
        accB.w += w0 * x0B.w + w1 * x1B.w;
    }
    for (; e < e1; e += 2) {
        int ei = e + half;
        bool valid = ei < e1;
        int src = __ldg(&g_CSR[valid ? ei : e]);
        uint4 u = __ldg((const uint4*)(XL + (size_t)src * 128) + hl);
        float4 xA, xB;
        unp16(u, xA, xB);
        float p = logit8(xA, xB, xrA, xrB, a6A, a4A, a6B, a4B);
        p += __shfl_xor_sync(0xFFFFFFFFu, p, 1);
        p += __shfl_xor_sync(0xFFFFFFFFu, p, 2);
        float w = valid ? __expf(p) : 0.f;
        s += w;
        accA.x += w * xA.x; accA.y += w * xA.y;
        accA.z += w * xA.z; accA.w += w * xA.w;
        accB.x += w * xB.x; accB.y += w * xB.y;
        accB.z += w * xB.z; accB.w += w * xB.w;
    }

    s += __shfl_xor_sync(0xFFFFFFFFu, s, 16);
    accA.x += __shfl_down_sync(0xFFFFFFFFu, accA.x, 16);
    accA.y += __shfl_down_sync(0xFFFFFFFFu, accA.y, 16);
    accA.z += __shfl_down_sync(0xFFFFFFFFu, accA.z, 16);
    accA.w += __shfl_down_sync(0xFFFFFFFFu, accA.w, 16);
    accB.x += __shfl_up_sync(0xFFFFFFFFu, accB.x, 16);
    accB.y += __shfl_up_sync(0xFFFFFFFFu, accB.y, 16);
    accB.z += __shfl_up_sync(0xFFFFFFFFu, accB.z, 16);
    accB.w += __shfl_up_sync(0xFFFFFFFFu, accB.w, 16);

    float inv = 1.f / (s + 1e-16f);
    float4 acc = half ? accB : accA;
    float4 b4 = __ldg((const float4*)bias + 2 * hl + half);
    float4 o;
    o.x = fmaxf(acc.x * inv + b4.x, 0.f);
    o.y = fmaxf(acc.y * inv + b4.y, 0.f);
    o.z = fmaxf(acc.z * inv + b4.z, 0.f);
    o.w = fmaxf(acc.w * inv + b4.w, 0.f);
    *((float4*)(out + (size_t)warp * 128) + 2 * hl + half) = o;
}

// ------------------------- launch --------------------------------------------
extern "C" void kernel_launch(void* const* d_in, const int* in_sizes, int n_in,
                              void* d_out, int out_size) {
    const float* x    = (const float*)d_in[0];
    const void*  ei   = d_in[1];
    const float* W1l  = (const float*)d_in[2];
    const float* W1r  = (const float*)d_in[3];
    const float* att1 = (const float*)d_in[4];
    const float* b1   = (const float*)d_in[5];
    const float* W2l  = (const float*)d_in[6];
    const float* W2r  = (const float*)d_in[7];
    const float* att2 = (const float*)d_in[8];
    const float* b2   = (const float*)d_in[9];
    float* out = (float*)d_out;

    __half *XL, *XR;
    float *H1;
    cudaGetSymbolAddress((void**)&XL, g_XLh);
    cudaGetSymbolAddress((void**)&XR, g_XRh);
    cudaGetSymbolAddress((void**)&H1, g_H1);

    static cudaStream_t s1 = nullptr;
    static cudaEvent_t evFork = nullptr, evG1 = nullptr;
    if (!s1) {
        cudaStreamCreateWithFlags(&s1, cudaStreamNonBlocking);
        cudaEventCreateWithFlags(&evFork, cudaEventDisableTiming);
        cudaEventCreateWithFlags(&evG1, cudaEventDisableTiming);
    }

    int gemm_grid = (N_NODES + 127) / 128;
    int agg_grid  = (N_NODES * 32 + 255) / 256;
    int nblk = (N_NODES + 1023) / 1024;

    // fork: layer-1 GEMM on side stream, concurrent with CSR build
    cudaEventRecord(evFork, 0);
    cudaStreamWaitEvent(s1, evFork, 0);
    k_gemm_tc<<<gemm_grid, 512, 0, s1>>>(x, W1l, W1r, XL, XR, N_NODES);
    cudaEventRecord(evG1, s1);

    // CSR build on main stream
    k_hist<<<(E_TOT + 255) / 256, 256>>>(ei);
    k_scanf<<<nblk, 1024>>>();
    k_scatter<<<(E_TOT + 255) / 256, 256>>>(ei);

    // join
    cudaStreamWaitEvent(0, evG1, 0);

    // layer 1 aggregate
    k_agg<<<agg_grid, 256>>>(XL, XR, att1, b1, H1);

    // layer 2
    k_gemm_tc<<<gemm_grid, 512>>>(H1, W2l, W2r, XL, XR, N_NODES);
    k_agg<<<agg_grid, 256>>>(XL, XR, att2, b2, out);
}

// round 14
// speedup vs baseline: 1.1481x; 1.0220x over previous
#include <cuda_runtime.h>
#include <cuda_fp16.h>
#include <math.h>
#include <stdint.h>

#define N_NODES 50000
#define N_EDGES 1600000
#define E_TOT   (N_EDGES + N_NODES)
#define HID     128
#define SLOPE   0.2f

// ------------------------- device scratch (no allocs allowed) ---------------
__device__ __half g_XLh[(size_t)N_NODES * HID];
__device__ __half g_XRh[(size_t)N_NODES * HID];
__device__ float  g_H1[(size_t)N_NODES * HID];
__device__ int    g_DEG[N_NODES];       // zero-init; k_scanf re-zeroes
__device__ int    g_ROWPTR[N_NODES + 1];
__device__ int    g_RANK[E_TOT];        // per-edge rank within its dst bucket
__device__ int    g_CSR[E_TOT];
__device__ int    g_PART[64];           // zeroed by k_hist block 0

// ------------------------- edge dtype helpers --------------------------------
__device__ __forceinline__ int detect_is64(const void* e) {
    int flag = (((const int*)e)[2 * threadIdx.x + 1] != 0);
    return !__syncthreads_or(flag);
}
__device__ __forceinline__ int edge_val(const void* e, int is64, int idx) {
    return is64 ? (int)((const long long*)e)[idx] : ((const int*)e)[idx];
}

// ------------------------- CSR build -----------------------------------------
__global__ __launch_bounds__(256) void k_hist(const void* __restrict__ e) {
    if (blockIdx.x == 0 && threadIdx.x < 64) g_PART[threadIdx.x] = 0;
    int is64 = detect_is64(e);
    int i = blockIdx.x * 256 + threadIdx.x;
    if (i >= E_TOT) return;
    int d = (i < N_EDGES) ? edge_val(e, is64, N_EDGES + i) : (i - N_EDGES);
    g_RANK[i] = atomicAdd(&g_DEG[d], 1);
}

__global__ __launch_bounds__(1024) void k_scanf() {
    __shared__ int s[1024];
    __shared__ int off_s;
    int i = blockIdx.x * 1024 + threadIdx.x;
    int v = (i < N_NODES) ? g_DEG[i] : 0;
    if (i < N_NODES) g_DEG[i] = 0;
    s[threadIdx.x] = v;
    __syncthreads();
    #pragma unroll
    for (int off = 1; off < 1024; off <<= 1) {
        int t = (threadIdx.x >= off) ? s[threadIdx.x - off] : 0;
        __syncthreads();
        s[threadIdx.x] += t;
        __syncthreads();
    }
    int incl = s[threadIdx.x];
    if (threadIdx.x == 1023)
        atomicExch(&g_PART[blockIdx.x], incl);   // partial >= 848 > 0
    if (threadIdx.x < 32) {
        int sum = 0;
        for (int b = threadIdx.x; b < (int)blockIdx.x; b += 32) {
            int t;
            do { t = atomicAdd(&g_PART[b], 0); } while (t == 0);
            sum += t;
        }
        #pragma unroll
        for (int d = 16; d > 0; d >>= 1)
            sum += __shfl_down_sync(0xFFFFFFFFu, sum, d);
        if (threadIdx.x == 0) off_s = sum;
    }
    __syncthreads();
    if (i < N_NODES)
        g_ROWPTR[i] = incl - v + off_s;
    if (i == 0) g_ROWPTR[N_NODES] = E_TOT;
}

__global__ __launch_bounds__(256) void k_scatter(const void* __restrict__ e) {
    int is64 = detect_is64(e);
    int i = blockIdx.x * 256 + threadIdx.x;
    if (i >= E_TOT) return;
    int s_, d_;
    if (i < N_EDGES) {
        s_ = edge_val(e, is64, i);
        d_ = edge_val(e, is64, N_EDGES + i);
    } else {
        s_ = d_ = i - N_EDGES;
    }
    int pos = __ldg(&g_ROWPTR[d_]) + __ldg(&g_RANK[i]);
    g_CSR[pos] = s_;
}

// ------------------------- fp16 tensor-core dual GEMM ------------------------
#define ASP_STRIDE 20
#define WSP_STRIDE 260

__device__ __forceinline__ void mma_f16(float4& d, const unsigned a[4], const unsigned b[2]) {
    asm volatile(
        "mma.sync.aligned.m16n8k16.row.col.f32.f16.f16.f32 "
        "{%0,%1,%2,%3}, {%4,%5,%6,%7}, {%8,%9}, {%0,%1,%2,%3};"
        : "+f"(d.x), "+f"(d.y), "+f"(d.z), "+f"(d.w)
        : "r"(a[0]), "r"(a[1]), "r"(a[2]), "r"(a[3]), "r"(b[0]), "r"(b[1]));
}

__global__ __launch_bounds__(512, 1) void k_gemm_tc(const float* __restrict__ A,
                                                    const float* __restrict__ Wl,
                                                    const float* __restrict__ Wr,
                                                    __half* __restrict__ XL,
                                                    __half* __restrict__ XR, int M) {
    __shared__ __half2 Asp[128][ASP_STRIDE];
    __shared__ __half2 Wsp[16][WSP_STRIDE];

    int tid = threadIdx.x;
    int wid = tid >> 5, lane = tid & 31;
    int g = lane >> 2, t = lane & 3;
    int wm = wid & 3, wn = wid >> 2;
    int m0 = blockIdx.x * 128;

    float4 C[2][8];
    #pragma unroll
    for (int i = 0; i < 2; i++)
        #pragma unroll
        for (int j = 0; j < 8; j++) C[i][j] = make_float4(0.f, 0.f, 0.f, 0.f);

    for (int k0 = 0; k0 < 128; k0 += 32) {
        #pragma unroll
        for (int j = 0; j < 2; j++) {
            int f = tid + 512 * j;
            int row = f >> 3, colf = (f & 7) * 4;
            float4 v = make_float4(0.f, 0.f, 0.f, 0.f);
            if (m0 + row < M)
                v = *(const float4*)(A + (size_t)(m0 + row) * 128 + k0 + colf);
            int c2 = colf >> 1;
            Asp[row][c2]     = __floats2half2_rn(v.x, v.y);
            Asp[row][c2 + 1] = __floats2half2_rn(v.z, v.w);
        }
        #pragma unroll
        for (int j = 0; j < 2; j++) {
            int f = tid + 512 * j;
            int k2 = f >> 6, nf = (f & 63) * 4;
            int k = k0 + 2 * k2;
            const float* W0 = (nf < 128) ? (Wl + (size_t)k * 128 + nf)
                                         : (Wr + (size_t)k * 128 + (nf - 128));
            const float* W1 = W0 + 128;
            float4 v0 = *(const float4*)W0;
            float4 v1 = *(const float4*)W1;
            Wsp[k2][nf]     = __floats2half2_rn(v0.x, v1.x);
            Wsp[k2][nf + 1] = __floats2half2_rn(v0.y, v1.y);
            Wsp[k2][nf + 2] = __floats2half2_rn(v0.z, v1.z);
            Wsp[k2][nf + 3] = __floats2half2_rn(v0.w, v1.w);
        }
        __syncthreads();

        #pragma unroll
        for (int ks2 = 0; ks2 < 16; ks2 += 8) {
            unsigned a[2][4], b[8][2];
            #pragma unroll
            for (int mt = 0; mt < 2; mt++) {
                int r = wm * 32 + mt * 16;
                a[mt][0] = *(const unsigned*)&Asp[r + g][ks2 + t];
                a[mt][1] = *(const unsigned*)&Asp[r + g + 8][ks2 + t];
                a[mt][2] = *(const unsigned*)&Asp[r + g][ks2 + t + 4];
                a[mt][3] = *(const unsigned*)&Asp[r + g + 8][ks2 + t + 4];
            }
            #pragma unroll
            for (int j = 0; j < 8; j++) {
                int n = wn * 64 + j * 8 + g;
                b[j][0] = *(const unsigned*)&Wsp[ks2 + t][n];
                b[j][1] = *(const unsigned*)&Wsp[ks2 + t + 4][n];
            }
            #pragma unroll
            for (int mt = 0; mt < 2; mt++)
                #pragma unroll
                for (int j = 0; j < 8; j++) mma_f16(C[mt][j], a[mt], b[j]);
        }
        __syncthreads();
    }

    __half* base = (wn < 2) ? XL : XR;
    int ncol0 = (wn & 1) * 64;
    #pragma unroll
    for (int mt = 0; mt < 2; mt++) {
        int r0 = m0 + wm * 32 + mt * 16 + g;
        #pragma unroll
        for (int j = 0; j < 8; j++) {
            int c = ncol0 + j * 8 + 2 * t;
            if (r0 < M)
                *(__half2*)(base + (size_t)r0 * 128 + c) = __floats2half2_rn(C[mt][j].x, C[mt][j].y);
            if (r0 + 8 < M)
                *(__half2*)(base + (size_t)(r0 + 8) * 128 + c) = __floats2half2_rn(C[mt][j].z, C[mt][j].w);
        }
    }
}

// ------------------------- GATv2 aggregation (v-trick) -----------------------
// Warp per dst node, two edges in flight per half-warp, 4-edge main loop.
// v = xl_src + xr computed in half2 (xr stays PACKED, 4 regs); accumulator
// runs on v:  Σw·xl = Σw·v − s·xr, recovered in the epilogue as
// out = acc·inv − xr + bias. Cuts live registers (~64 → ~54) so
// __launch_bounds__(128, 9) reaches 56% occupancy without spills.
__device__ __forceinline__ void addunp(uint4 u, uint4 xr, float4& A, float4& B) {
    __half2 v0 = __hadd2(*reinterpret_cast<__half2*>(&u.x), *reinterpret_cast<__half2*>(&xr.x));
    __half2 v1 = __hadd2(*reinterpret_cast<__half2*>(&u.y), *reinterpret_cast<__half2*>(&xr.y));
    __half2 v2 = __hadd2(*reinterpret_cast<__half2*>(&u.z), *reinterpret_cast<__half2*>(&xr.z));
    __half2 v3 = __hadd2(*reinterpret_cast<__half2*>(&u.w), *reinterpret_cast<__half2*>(&xr.w));
    float2 f0 = __half22float2(v0);
    float2 f1 = __half22float2(v1);
    float2 f2 = __half22float2(v2);
    float2 f3 = __half22float2(v3);
    A = make_float4(f0.x, f0.y, f1.x, f1.y);
    B = make_float4(f2.x, f2.y, f3.x, f3.y);
}

__device__ __forceinline__ float logitv(const float4& vA, const float4& vB,
                                        const float4& a6A, const float4& a4A,
                                        const float4& a6B, const float4& a4B) {
    float p = a6A.x * vA.x + a4A.x * fabsf(vA.x);
    p = fmaf(a6A.y, vA.y, fmaf(a4A.y, fabsf(vA.y), p));
    p = fmaf(a6A.z, vA.z, fmaf(a4A.z, fabsf(vA.z), p));
    p = fmaf(a6A.w, vA.w, fmaf(a4A.w, fabsf(vA.w), p));
    p = fmaf(a6B.x, vB.x, fmaf(a4B.x, fabsf(vB.x), p));
    p = fmaf(a6B.y, vB.y, fmaf(a4B.y, fabsf(vB.y), p));
    p = fmaf(a6B.z, vB.z, fmaf(a4B.z, fabsf(vB.z), p));
    p = fmaf(a6B.w, vB.w, fmaf(a4B.w, fabsf(vB.w), p));
    return p;
}

__global__ __launch_bounds__(128, 9) void k_agg(const __half* __restrict__ XL,
                                                const __half* __restrict__ XR,
                                                const float* __restrict__ att,
                                                const float* __restrict__ bias,
                                                float* __restrict__ out) {
    int warp = (blockIdx.x * blockDim.x + threadIdx.x) >> 5;
    int lane = threadIdx.x & 31;
    if (warp >= N_NODES) return;
    int half = lane >> 4;
    int hl   = lane & 15;

    const float4* attp = (const float4*)att;
    float4 aA = __ldg(attp + 2 * hl), aB = __ldg(attp + 2 * hl + 1);
    float4 a6A = make_float4(0.6f * aA.x, 0.6f * aA.y, 0.6f * aA.z, 0.6f * aA.w);
    float4 a4A = make_float4(0.4f * aA.x, 0.4f * aA.y, 0.4f * aA.z, 0.4f * aA.w);
    float4 a6B = make_float4(0.6f * aB.x, 0.6f * aB.y, 0.6f * aB.z, 0.6f * aB.w);
    float4 a4B = make_float4(0.4f * aB.x, 0.4f * aB.y, 0.4f * aB.z, 0.4f * aB.w);

    uint4 xru = __ldg((const uint4*)(XR + (size_t)warp * 128) + hl);  // packed

    int e0 = __ldg(&g_ROWPTR[warp]);
    int e1 = __ldg(&g_ROWPTR[warp + 1]);

    float s = 0.f;
    float4 accA = make_float4(0.f, 0.f, 0.f, 0.f);   // Σ w·v, channels A
    float4 accB = make_float4(0.f, 0.f, 0.f, 0.f);   // Σ w·v, channels B

    int e = e0;
    for (; e + 4 <= e1; e += 4) {
        int s0 = __ldg(&g_CSR[e + half]);
        int s1 = __ldg(&g_CSR[e + 2 + half]);
        uint4 u0 = __ldg((const uint4*)(XL + (size_t)s0 * 128) + hl);
        uint4 u1 = __ldg((const uint4*)(XL + (size_t)s1 * 128) + hl);
        float4 v0A, v0B, v1A, v1B;
        addunp(u0, xru, v0A, v0B);
        addunp(u1, xru, v1A, v1B);

        float p0 = logitv(v0A, v0B, a6A, a4A, a6B, a4B);
        float p1 = logitv(v1A, v1B, a6A, a4A, a6B, a4B);
        p0 += __shfl_xor_sync(0xFFFFFFFFu, p0, 1);
        p1 += __shfl_xor_sync(0xFFFFFFFFu, p1, 1);
        p0 += __shfl_xor_sync(0xFFFFFFFFu, p0, 2);
        p1 += __shfl_xor_sync(0xFFFFFFFFu, p1, 2);
        float w0 = __expf(p0), w1 = __expf(p1);

        s += w0 + w1;
        accA.x += w0 * v0A.x + w1 * v1A.x;
        accA.y += w0 * v0A.y + w1 * v1A.y;
        accA.z += w0 * v0A.z + w1 * v1A.z;
        accA.w += w0 * v0A.w + w1 * v1A.w;
        accB.x += w0 * v0B.x + w1 * v1B.x;
        accB.y += w0 * v0B.y + w1 * v1B.y;
        accB.z += w0 * v0B.z + w1 * v1B.z;
        accB.w += w0 * v0B.w + w1 * v1B.w;
    }
    for (; e < e1; e += 2) {
        int ei = e + half;
        bool valid = ei < e1;
        int src = __ldg(&g_CSR[valid ? ei : e]);
        uint4 u = __ldg((const uint4*)(XL + (size_t)src * 128) + hl);
        float4 vA, vB;
        addunp(u, xru, vA, vB);
        float p = logitv(vA, vB, a6A, a4A, a6B, a4B);
        p += __shfl_xor_sync(0xFFFFFFFFu, p, 1);
        p += __shfl_xor_sync(0xFFFFFFFFu, p, 2);
        float w = valid ? __expf(p) : 0.f;
        s += w;
        accA.x += w * vA.x; accA.y += w * vA.y;
        accA.z += w * vA.z; accA.w += w * vA.w;
        accB.x += w * vB.x; accB.y += w * vB.y;
        accB.z += w * vB.z; accB.w += w * vB.w;
    }

    // merge halves
    s += __shfl_xor_sync(0xFFFFFFFFu, s, 16);
    accA.x += __shfl_down_sync(0xFFFFFFFFu, accA.x, 16);
    accA.y += __shfl_down_sync(0xFFFFFFFFu, accA.y, 16);
    accA.z += __shfl_down_sync(0xFFFFFFFFu, accA.z, 16);
    accA.w += __shfl_down_sync(0xFFFFFFFFu, accA.w, 16);
    accB.x += __shfl_up_sync(0xFFFFFFFFu, accB.x, 16);
    accB.y += __shfl_up_sync(0xFFFFFFFFu, accB.y, 16);
    accB.z += __shfl_up_sync(0xFFFFFFFFu, accB.z, 16);
    accB.w += __shfl_up_sync(0xFFFFFFFFu, accB.w, 16);

    // epilogue: out = acc/s - xr + bias, relu
    float inv = 1.f / (s + 1e-16f);
    float4 acc = half ? accB : accA;
    // unpack my half's xr channels
    float2 x0 = __half22float2(*reinterpret_cast<__half2*>(half ? &xru.z : &xru.x));
    float2 x1 = __half22float2(*reinterpret_cast<__half2*>(half ? &xru.w : &xru.y));
    float4 b4 = __ldg((const float4*)bias + 2 * hl + half);
    float4 o;
    o.x = fmaxf(acc.x * inv - x0.x + b4.x, 0.f);
    o.y = fmaxf(acc.y * inv - x0.y + b4.y, 0.f);
    o.z = fmaxf(acc.z * inv - x1.x + b4.z, 0.f);
    o.w = fmaxf(acc.w * inv - x1.y + b4.w, 0.f);
    *((float4*)(out + (size_t)warp * 128) + 2 * hl + half) = o;
}

// ------------------------- launch --------------------------------------------
extern "C" void kernel_launch(void* const* d_in, const int* in_sizes, int n_in,
                              void* d_out, int out_size) {
    const float* x    = (const float*)d_in[0];
    const void*  ei   = d_in[1];
    const float* W1l  = (const float*)d_in[2];
    const float* W1r  = (const float*)d_in[3];
    const float* att1 = (const float*)d_in[4];
    const float* b1   = (const float*)d_in[5];
    const float* W2l  = (const float*)d_in[6];
    const float* W2r  = (const float*)d_in[7];
    const float* att2 = (const float*)d_in[8];
    const float* b2   = (const float*)d_in[9];
    float* out = (float*)d_out;

    __half *XL, *XR;
    float *H1;
    cudaGetSymbolAddress((void**)&XL, g_XLh);
    cudaGetSymbolAddress((void**)&XR, g_XRh);
    cudaGetSymbolAddress((void**)&H1, g_H1);

    static cudaStream_t s1 = nullptr;
    static cudaEvent_t evFork = nullptr, evG1 = nullptr;
    if (!s1) {
        cudaStreamCreateWithFlags(&s1, cudaStreamNonBlocking);
        cudaEventCreateWithFlags(&evFork, cudaEventDisableTiming);
        cudaEventCreateWithFlags(&evG1, cudaEventDisableTiming);
    }

    int gemm_grid = (N_NODES + 127) / 128;
    int agg_grid  = (N_NODES * 32 + 127) / 128;
    int nblk = (N_NODES + 1023) / 1024;

    // fork: layer-1 GEMM on side stream, concurrent with CSR build
    cudaEventRecord(evFork, 0);
    cudaStreamWaitEvent(s1, evFork, 0);
    k_gemm_tc<<<gemm_grid, 512, 0, s1>>>(x, W1l, W1r, XL, XR, N_NODES);
    cudaEventRecord(evG1, s1);

    // CSR build on main stream
    k_hist<<<(E_TOT + 255) / 256, 256>>>(ei);
    k_scanf<<<nblk, 1024>>>();
    k_scatter<<<(E_TOT + 255) / 256, 256>>>(ei);

    // join
    cudaStreamWaitEvent(0, evG1, 0);

    // layer 1 aggregate
    k_agg<<<agg_grid, 128>>>(XL, XR, att1, b1, H1);

    // layer 2
    k_gemm_tc<<<gemm_grid, 512>>>(H1, W2l, W2r, XL, XR, N_NODES);
    k_agg<<<agg_grid, 128>>>(XL, XR, att2, b2, out);
}

// round 15
// speedup vs baseline: 1.1802x; 1.0279x over previous
#include <cuda_runtime.h>
#include <cuda_fp16.h>
#include <math.h>
#include <stdint.h>

#define N_NODES 50000
#define N_EDGES 1600000
#define E_TOT   (N_EDGES + N_NODES)
#define HID     128
#define SLOPE   0.2f

// ------------------------- device scratch (no allocs allowed) ---------------
__device__ __half g_XLh[(size_t)N_NODES * HID];
__device__ __half g_XRh[(size_t)N_NODES * HID];
__device__ float  g_H1[(size_t)N_NODES * HID];
__device__ int    g_DEG[N_NODES];       // zero-init; k_scanf re-zeroes
__device__ int    g_ROWPTR[N_NODES + 1];
__device__ int    g_RANK[E_TOT];        // per-edge rank within its dst bucket
__device__ int    g_CSR[E_TOT];
__device__ int    g_PART[64];           // zeroed by k_hist block 0

// ------------------------- edge dtype helpers --------------------------------
__device__ __forceinline__ int detect_is64(const void* e) {
    int flag = (((const int*)e)[2 * threadIdx.x + 1] != 0);
    return !__syncthreads_or(flag);
}
__device__ __forceinline__ int edge_val(const void* e, int is64, int idx) {
    return is64 ? (int)((const long long*)e)[idx] : ((const int*)e)[idx];
}
// load 2 consecutive edge values starting at even idx
__device__ __forceinline__ int2 edge_val2(const void* e, int is64, int idx) {
    if (is64) {
        int4 a = __ldg((const int4*)((const long long*)e + idx));
        return make_int2(a.x, a.z);
    } else {
        return __ldg((const int2*)((const int*)e + idx));
    }
}

// ------------------------- CSR build (2 edges / thread) ----------------------
__global__ __launch_bounds__(256) void k_hist(const void* __restrict__ e) {
    if (blockIdx.x == 0 && threadIdx.x < 64) g_PART[threadIdx.x] = 0;
    int is64 = detect_is64(e);
    int base = (blockIdx.x * 256 + threadIdx.x) * 2;
    if (base >= E_TOT) return;
    int d0, d1;
    if (base < N_EDGES) {                  // N_EDGES % 2 == 0: pair inside
        int2 d = edge_val2(e, is64, N_EDGES + base);
        d0 = d.x; d1 = d.y;
    } else {
        d0 = base - N_EDGES; d1 = d0 + 1;
    }
    int r0 = atomicAdd(&g_DEG[d0], 1);
    int r1 = atomicAdd(&g_DEG[d1], 1);
    *(int2*)&g_RANK[base] = make_int2(r0, r1);
}

__global__ __launch_bounds__(1024) void k_scanf() {
    __shared__ int s[1024];
    __shared__ int off_s;
    int i = blockIdx.x * 1024 + threadIdx.x;
    int v = (i < N_NODES) ? g_DEG[i] : 0;
    if (i < N_NODES) g_DEG[i] = 0;
    s[threadIdx.x] = v;
    __syncthreads();
    #pragma unroll
    for (int off = 1; off < 1024; off <<= 1) {
        int t = (threadIdx.x >= off) ? s[threadIdx.x - off] : 0;
        __syncthreads();
        s[threadIdx.x] += t;
        __syncthreads();
    }
    int incl = s[threadIdx.x];
    if (threadIdx.x == 1023)
        atomicExch(&g_PART[blockIdx.x], incl);   // partial >= 848 > 0
    if (threadIdx.x < 32) {
        int sum = 0;
        for (int b = threadIdx.x; b < (int)blockIdx.x; b += 32) {
            int t;
            do { t = atomicAdd(&g_PART[b], 0); } while (t == 0);
            sum += t;
        }
        #pragma unroll
        for (int d = 16; d > 0; d >>= 1)
            sum += __shfl_down_sync(0xFFFFFFFFu, sum, d);
        if (threadIdx.x == 0) off_s = sum;
    }
    __syncthreads();
    if (i < N_NODES)
        g_ROWPTR[i] = incl - v + off_s;
    if (i == 0) g_ROWPTR[N_NODES] = E_TOT;
}

// scatter: atomic-free, 2 edges/thread — pos = ROWPTR[dst] + RANK[i]
__global__ __launch_bounds__(256) void k_scatter(const void* __restrict__ e) {
    int is64 = detect_is64(e);
    int base = (blockIdx.x * 256 + threadIdx.x) * 2;
    if (base >= E_TOT) return;
    int s0, s1, d0, d1;
    if (base < N_EDGES) {
        int2 sv = edge_val2(e, is64, base);
        int2 dv = edge_val2(e, is64, N_EDGES + base);
        s0 = sv.x; s1 = sv.y; d0 = dv.x; d1 = dv.y;
    } else {
        s0 = d0 = base - N_EDGES;
        s1 = d1 = s0 + 1;
    }
    int2 rk = __ldg((const int2*)&g_RANK[base]);
    int p0 = __ldg(&g_ROWPTR[d0]) + rk.x;
    int p1 = __ldg(&g_ROWPTR[d1]) + rk.y;
    g_CSR[p0] = s0;
    g_CSR[p1] = s1;
}

// ------------------------- fp16 tensor-core dual GEMM ------------------------
#define ASP_STRIDE 20
#define WSP_STRIDE 260

__device__ __forceinline__ void mma_f16(float4& d, const unsigned a[4], const unsigned b[2]) {
    asm volatile(
        "mma.sync.aligned.m16n8k16.row.col.f32.f16.f16.f32 "
        "{%0,%1,%2,%3}, {%4,%5,%6,%7}, {%8,%9}, {%0,%1,%2,%3};"
        : "+f"(d.x), "+f"(d.y), "+f"(d.z), "+f"(d.w)
        : "r"(a[0]), "r"(a[1]), "r"(a[2]), "r"(a[3]), "r"(b[0]), "r"(b[1]));
}

__global__ __launch_bounds__(512, 1) void k_gemm_tc(const float* __restrict__ A,
                                                    const float* __restrict__ Wl,
                                                    const float* __restrict__ Wr,
                                                    __half* __restrict__ XL,
                                                    __half* __restrict__ XR, int M) {
    __shared__ __half2 Asp[128][ASP_STRIDE];
    __shared__ __half2 Wsp[16][WSP_STRIDE];

    int tid = threadIdx.x;
    int wid = tid >> 5, lane = tid & 31;
    int g = lane >> 2, t = lane & 3;
    int wm = wid & 3, wn = wid >> 2;
    int m0 = blockIdx.x * 128;

    float4 C[2][8];
    #pragma unroll
    for (int i = 0; i < 2; i++)
        #pragma unroll
        for (int j = 0; j < 8; j++) C[i][j] = make_float4(0.f, 0.f, 0.f, 0.f);

    for (int k0 = 0; k0 < 128; k0 += 32) {
        #pragma unroll
        for (int j = 0; j < 2; j++) {
            int f = tid + 512 * j;
            int row = f >> 3, colf = (f & 7) * 4;
            float4 v = make_float4(0.f, 0.f, 0.f, 0.f);
            if (m0 + row < M)
                v = *(const float4*)(A + (size_t)(m0 + row) * 128 + k0 + colf);
            int c2 = colf >> 1;
            Asp[row][c2]     = __floats2half2_rn(v.x, v.y);
            Asp[row][c2 + 1] = __floats2half2_rn(v.z, v.w);
        }
        #pragma unroll
        for (int j = 0; j < 2; j++) {
            int f = tid + 512 * j;
            int k2 = f >> 6, nf = (f & 63) * 4;
            int k = k0 + 2 * k2;
            const float* W0 = (nf < 128) ? (Wl + (size_t)k * 128 + nf)
                                         : (Wr + (size_t)k * 128 + (nf - 128));
            const float* W1 = W0 + 128;
            float4 v0 = *(const float4*)W0;
            float4 v1 = *(const float4*)W1;
            Wsp[k2][nf]     = __floats2half2_rn(v0.x, v1.x);
            Wsp[k2][nf + 1] = __floats2half2_rn(v0.y, v1.y);
            Wsp[k2][nf + 2] = __floats2half2_rn(v0.z, v1.z);
            Wsp[k2][nf + 3] = __floats2half2_rn(v0.w, v1.w);
        }
        __syncthreads();

        #pragma unroll
        for (int ks2 = 0; ks2 < 16; ks2 += 8) {
            unsigned a[2][4], b[8][2];
            #pragma unroll
            for (int mt = 0; mt < 2; mt++) {
                int r = wm * 32 + mt * 16;
                a[mt][0] = *(const unsigned*)&Asp[r + g][ks2 + t];
                a[mt][1] = *(const unsigned*)&Asp[r + g + 8][ks2 + t];
                a[mt][2] = *(const unsigned*)&Asp[r + g][ks2 + t + 4];
                a[mt][3] = *(const unsigned*)&Asp[r + g + 8][ks2 + t + 4];
            }
            #pragma unroll
            for (int j = 0; j < 8; j++) {
                int n = wn * 64 + j * 8 + g;
                b[j][0] = *(const unsigned*)&Wsp[ks2 + t][n];
                b[j][1] = *(const unsigned*)&Wsp[ks2 + t + 4][n];
            }
            #pragma unroll
            for (int mt = 0; mt < 2; mt++)
                #pragma unroll
                for (int j = 0; j < 8; j++) mma_f16(C[mt][j], a[mt], b[j]);
        }
        __syncthreads();
    }

    __half* base = (wn < 2) ? XL : XR;
    int ncol0 = (wn & 1) * 64;
    #pragma unroll
    for (int mt = 0; mt < 2; mt++) {
        int r0 = m0 + wm * 32 + mt * 16 + g;
        #pragma unroll
        for (int j = 0; j < 8; j++) {
            int c = ncol0 + j * 8 + 2 * t;
            if (r0 < M)
                *(__half2*)(base + (size_t)r0 * 128 + c) = __floats2half2_rn(C[mt][j].x, C[mt][j].y);
            if (r0 + 8 < M)
                *(__half2*)(base + (size_t)(r0 + 8) * 128 + c) = __floats2half2_rn(C[mt][j].z, C[mt][j].w);
        }
    }
}

// ------------------------- GATv2 aggregation (v-trick + CSR prefetch) --------
__device__ __forceinline__ void addunp(uint4 u, uint4 xr, float4& A, float4& B) {
    __half2 v0 = __hadd2(*reinterpret_cast<__half2*>(&u.x), *reinterpret_cast<__half2*>(&xr.x));
    __half2 v1 = __hadd2(*reinterpret_cast<__half2*>(&u.y), *reinterpret_cast<__half2*>(&xr.y));
    __half2 v2 = __hadd2(*reinterpret_cast<__half2*>(&u.z), *reinterpret_cast<__half2*>(&xr.z));
    __half2 v3 = __hadd2(*reinterpret_cast<__half2*>(&u.w), *reinterpret_cast<__half2*>(&xr.w));
    float2 f0 = __half22float2(v0);
    float2 f1 = __half22float2(v1);
    float2 f2 = __half22float2(v2);
    float2 f3 = __half22float2(v3);
    A = make_float4(f0.x, f0.y, f1.x, f1.y);
    B = make_float4(f2.x, f2.y, f3.x, f3.y);
}

__device__ __forceinline__ float logitv(const float4& vA, const float4& vB,
                                        const float4& a6A, const float4& a4A,
                                        const float4& a6B, const float4& a4B) {
    float p = a6A.x * vA.x + a4A.x * fabsf(vA.x);
    p = fmaf(a6A.y, vA.y, fmaf(a4A.y, fabsf(vA.y), p));
    p = fmaf(a6A.z, vA.z, fmaf(a4A.z, fabsf(vA.z), p));
    p = fmaf(a6A.w, vA.w, fmaf(a4A.w, fabsf(vA.w), p));
    p = fmaf(a6B.x, vB.x, fmaf(a4B.x, fabsf(vB.x), p));
    p = fmaf(a6B.y, vB.y, fmaf(a4B.y, fabsf(vB.y), p));
    p = fmaf(a6B.z, vB.z, fmaf(a4B.z, fabsf(vB.z), p));
    p = fmaf(a6B.w, vB.w, fmaf(a4B.w, fabsf(vB.w), p));
    return p;
}

__global__ __launch_bounds__(128, 9) void k_agg(const __half* __restrict__ XL,
                                                const __half* __restrict__ XR,
                                                const float* __restrict__ att,
                                                const float* __restrict__ bias,
                                                float* __restrict__ out) {
    int warp = (blockIdx.x * blockDim.x + threadIdx.x) >> 5;
    int lane = threadIdx.x & 31;
    if (warp >= N_NODES) return;
    int half = lane >> 4;
    int hl   = lane & 15;

    const float4* attp = (const float4*)att;
    float4 aA = __ldg(attp + 2 * hl), aB = __ldg(attp + 2 * hl + 1);
    float4 a6A = make_float4(0.6f * aA.x, 0.6f * aA.y, 0.6f * aA.z, 0.6f * aA.w);
    float4 a4A = make_float4(0.4f * aA.x, 0.4f * aA.y, 0.4f * aA.z, 0.4f * aA.w);
    float4 a6B = make_float4(0.6f * aB.x, 0.6f * aB.y, 0.6f * aB.z, 0.6f * aB.w);
    float4 a4B = make_float4(0.4f * aB.x, 0.4f * aB.y, 0.4f * aB.z, 0.4f * aB.w);

    uint4 xru = __ldg((const uint4*)(XR + (size_t)warp * 128) + hl);  // packed

    int e0 = __ldg(&g_ROWPTR[warp]);
    int e1 = __ldg(&g_ROWPTR[warp + 1]);

    float s = 0.f;
    float4 accA = make_float4(0.f, 0.f, 0.f, 0.f);
    float4 accB = make_float4(0.f, 0.f, 0.f, 0.f);

    int e = e0;
    int nIter = (e1 - e0) >> 2;
    int sA, sB;
    if (nIter > 0) {
        sA = __ldg(&g_CSR[e + half]);
        sB = __ldg(&g_CSR[e + 2 + half]);
    }
    for (int it = 0; it < nIter; it++) {
        int s0 = sA, s1 = sB;
        int en = e + 4;
        if (it + 1 < nIter) {                 // prefetch next iteration's indices
            sA = __ldg(&g_CSR[en + half]);
            sB = __ldg(&g_CSR[en + 2 + half]);
        }
        uint4 u0 = __ldg((const uint4*)(XL + (size_t)s0 * 128) + hl);
        uint4 u1 = __ldg((const uint4*)(XL + (size_t)s1 * 128) + hl);
        float4 v0A, v0B, v1A, v1B;
        addunp(u0, xru, v0A, v0B);
        addunp(u1, xru, v1A, v1B);

        float p0 = logitv(v0A, v0B, a6A, a4A, a6B, a4B);
        float p1 = logitv(v1A, v1B, a6A, a4A, a6B, a4B);
        p0 += __shfl_xor_sync(0xFFFFFFFFu, p0, 1);
        p1 += __shfl_xor_sync(0xFFFFFFFFu, p1, 1);
        p0 += __shfl_xor_sync(0xFFFFFFFFu, p0, 2);
        p1 += __shfl_xor_sync(0xFFFFFFFFu, p1, 2);
        float w0 = __expf(p0), w1 = __expf(p1);

        s += w0 + w1;
        accA.x += w0 * v0A.x + w1 * v1A.x;
        accA.y += w0 * v0A.y + w1 * v1A.y;
        accA.z += w0 * v0A.z + w1 * v1A.z;
        accA.w += w0 * v0A.w + w1 * v1A.w;
        accB.x += w0 * v0B.x + w1 * v1B.x;
        accB.y += w0 * v0B.y + w1 * v1B.y;
        accB.z += w0 * v0B.z + w1 * v1B.z;
        accB.w += w0 * v0B.w + w1 * v1B.w;
        e = en;
    }
    for (; e < e1; e += 2) {
        int ei = e + half;
        bool valid = ei < e1;
        int src = __ldg(&g_CSR[valid ? ei : e]);
        uint4 u = __ldg((const uint4*)(XL + (size_t)src * 128) + hl);
        float4 vA, vB;
        addunp(u, xru, vA, vB);
        float p = logitv(vA, vB, a6A, a4A, a6B, a4B);
        p += __shfl_xor_sync(0xFFFFFFFFu, p, 1);
        p += __shfl_xor_sync(0xFFFFFFFFu, p, 2);
        float w = valid ? __expf(p) : 0.f;
        s += w;
        accA.x += w * vA.x; accA.y += w * vA.y;
        accA.z += w * vA.z; accA.w += w * vA.w;
        accB.x += w * vB.x; accB.y += w * vB.y;
        accB.z += w * vB.z; accB.w += w * vB.w;
    }

    // merge halves
    s += __shfl_xor_sync(0xFFFFFFFFu, s, 16);
    accA.x += __shfl_down_sync(0xFFFFFFFFu, accA.x, 16);
    accA.y += __shfl_down_sync(0xFFFFFFFFu, accA.y, 16);
    accA.z += __shfl_down_sync(0xFFFFFFFFu, accA.z, 16);
    accA.w += __shfl_down_sync(0xFFFFFFFFu, accA.w, 16);
    accB.x += __shfl_up_sync(0xFFFFFFFFu, accB.x, 16);
    accB.y += __shfl_up_sync(0xFFFFFFFFu, accB.y, 16);
    accB.z += __shfl_up_sync(0xFFFFFFFFu, accB.z, 16);
    accB.w += __shfl_up_sync(0xFFFFFFFFu, accB.w, 16);

    // epilogue: out = acc/s - xr + bias, relu
    float inv = 1.f / (s + 1e-16f);
    float4 acc = half ? accB : accA;
    float2 x0 = __half22float2(*reinterpret_cast<__half2*>(half ? &xru.z : &xru.x));
    float2 x1 = __half22float2(*reinterpret_cast<__half2*>(half ? &xru.w : &xru.y));
    float4 b4 = __ldg((const float4*)bias + 2 * hl + half);
    float4 o;
    o.x = fmaxf(acc.x * inv - x0.x + b4.x, 0.f);
    o.y = fmaxf(acc.y * inv - x0.y + b4.y, 0.f);
    o.z = fmaxf(acc.z * inv - x1.x + b4.z, 0.f);
    o.w = fmaxf(acc.w * inv - x1.y + b4.w, 0.f);
    *((float4*)(out + (size_t)warp * 128) + 2 * hl + half) = o;
}

// ------------------------- launch --------------------------------------------
extern "C" void kernel_launch(void* const* d_in, const int* in_sizes, int n_in,
                              void* d_out, int out_size) {
    const float* x    = (const float*)d_in[0];
    const void*  ei   = d_in[1];
    const float* W1l  = (const float*)d_in[2];
    const float* W1r  = (const float*)d_in[3];
    const float* att1 = (const float*)d_in[4];
    const float* b1   = (const float*)d_in[5];
    const float* W2l  = (const float*)d_in[6];
    const float* W2r  = (const float*)d_in[7];
    const float* att2 = (const float*)d_in[8];
    const float* b2   = (const float*)d_in[9];
    float* out = (float*)d_out;

    __half *XL, *XR;
    float *H1;
    cudaGetSymbolAddress((void**)&XL, g_XLh);
    cudaGetSymbolAddress((void**)&XR, g_XRh);
    cudaGetSymbolAddress((void**)&H1, g_H1);

    static cudaStream_t s1 = nullptr;
    static cudaEvent_t evFork = nullptr, evG1 = nullptr;
    if (!s1) {
        cudaStreamCreateWithFlags(&s1, cudaStreamNonBlocking);
        cudaEventCreateWithFlags(&evFork, cudaEventDisableTiming);
        cudaEventCreateWithFlags(&evG1, cudaEventDisableTiming);
    }

    int gemm_grid = (N_NODES + 127) / 128;
    int agg_grid  = (N_NODES * 32 + 127) / 128;
    int nblk = (N_NODES + 1023) / 1024;
    int edge2_grid = (E_TOT / 2 + 255) / 256;

    // fork: layer-1 GEMM on side stream, concurrent with CSR build
    cudaEventRecord(evFork, 0);
    cudaStreamWaitEvent(s1, evFork, 0);
    k_gemm_tc<<<gemm_grid, 512, 0, s1>>>(x, W1l, W1r, XL, XR, N_NODES);
    cudaEventRecord(evG1, s1);

    // CSR build on main stream (2 edges/thread hist + scatter)
    k_hist<<<edge2_grid, 256>>>(ei);
    k_scanf<<<nblk, 1024>>>();
    k_scatter<<<edge2_grid, 256>>>(ei);

    // join
    cudaStreamWaitEvent(0, evG1, 0);

    // layer 1 aggregate
    k_agg<<<agg_grid, 128>>>(XL, XR, att1, b1, H1);

    // layer 2
    k_gemm_tc<<<gemm_grid, 512>>>(H1, W2l, W2r, XL, XR, N_NODES);
    k_agg<<<agg_grid, 128>>>(XL, XR, att2, b2, out);
}